// round 7
// baseline (speedup 1.0000x reference)
#include <cuda_runtime.h>
#include <cuda_fp16.h>
#include <cstdint>

// ---------------------------------------------------------------------------
// B=32, CIN=256, COUT=256, 64x64 -> 32x32, 3x3 stride2 pad1 conv. Crop mask
// all-True => plain conv. Round 7: fp16 m16n8k16 two-term split GEMM:
//   C = Ahi*Bhi + Alo*Bhi   (weights split hi/lo fp16, x single fp16)
// 3-stage bulk-copy pipeline, 512 threads, fused transform prologue.
// ---------------------------------------------------------------------------

#define B_    32
#define CIN_  256
#define COUT_ 256
#define H_    64
#define W_    64
#define HW_   4096
#define NPIX_ 1024

#define BM 128
#define BN 256
#define KC 64
#define NIT 36                 // 9 taps * 4 cin-chunks

// fp16 rows: 64 fp16 = 128B payload, 144B stride (bank = 4*lg + lc, conflict-free)
#define ROW_B    144
#define AH_OFF   0
#define AL_OFF   (128 * ROW_B)             // 18432
#define B_OFF2   (2 * 128 * ROW_B)         // 36864
#define STAGE_B  (B_OFF2 + 256 * ROW_B)    // 73728
#define TILES_OFF 1024
#define NSTAGE   3
#define SMEM_TOTAL (TILES_OFF + NSTAGE * STAGE_B)   // 222208

__device__ __align__(128) __half g_Ah[9 * COUT_ * CIN_];        // [p][cout][cin]
__device__ __align__(128) __half g_Al[9 * COUT_ * CIN_];
__device__ __align__(128) __half g_X[(size_t)B_ * HW_ * CIN_];  // [b][s][cin] 67MB

// ---------------------------------------------------------------------------
__device__ __forceinline__ uint32_t smem_u32(const void* p) {
    uint32_t a;
    asm("{ .reg .u64 t; cvta.to.shared.u64 t, %1; cvt.u32.u64 %0, t; }" : "=r"(a) : "l"(p));
    return a;
}
__device__ __forceinline__ void bulk_g2s(uint32_t dst, const void* src, uint32_t bytes,
                                         uint32_t mbar) {
    asm volatile(
        "cp.async.bulk.shared::cluster.global.mbarrier::complete_tx::bytes "
        "[%0], [%1], %2, [%3];"
        :: "r"(dst), "l"(src), "r"(bytes), "r"(mbar) : "memory");
}
__device__ __forceinline__ void mbar_init(uint32_t a, uint32_t cnt) {
    asm volatile("mbarrier.init.shared.b64 [%0], %1;" :: "r"(a), "r"(cnt) : "memory");
}
__device__ __forceinline__ void mbar_expect_tx(uint32_t a, uint32_t tx) {
    asm volatile("mbarrier.arrive.expect_tx.shared.b64 _, [%0], %1;"
                 :: "r"(a), "r"(tx) : "memory");
}
__device__ __forceinline__ void mbar_wait(uint32_t a, uint32_t parity) {
    asm volatile(
        "{\n\t.reg .pred P1;\n\t"
        "W_%=:\n\t"
        "mbarrier.try_wait.parity.acquire.cta.shared::cta.b64 P1, [%0], %1, 0x989680;\n\t"
        "@!P1 bra W_%=;\n\t}"
        :: "r"(a), "r"(parity) : "memory");
}
__device__ __forceinline__ void mma_fp16(float* d, const uint32_t* a, uint32_t b0, uint32_t b1) {
    asm volatile(
        "mma.sync.aligned.m16n8k16.row.col.f32.f16.f16.f32 "
        "{%0,%1,%2,%3}, {%4,%5,%6,%7}, {%8,%9}, {%0,%1,%2,%3};"
        : "+f"(d[0]), "+f"(d[1]), "+f"(d[2]), "+f"(d[3])
        : "r"(a[0]), "r"(a[1]), "r"(a[2]), "r"(a[3]), "r"(b0), "r"(b1));
}
__device__ __forceinline__ uint32_t lds32(uint32_t addr) {
    uint32_t v;
    asm volatile("ld.shared.b32 %0, [%1];" : "=r"(v) : "r"(addr));
    return v;
}

// ---------------------------------------------------------------------------
// Fused prologue: blocks [0, 2304) -> weight split; [2304, 35072) -> x convert
// ---------------------------------------------------------------------------
__global__ void transform_kernel(const float* __restrict__ x, const float* __restrict__ w) {
    __shared__ float tile[32][33];
    const int tid = threadIdx.x;
    if (blockIdx.x < 2304) {
        int idx = blockIdx.x * 256 + tid;           // over [p][cout][cin]
        int cin = idx & 255;
        int cout = (idx >> 8) & 255;
        int p = idx >> 16;
        float v = w[cout * (CIN_ * 9) + cin * 9 + p];
        __half hi = __float2half_rn(v);
        g_Ah[idx] = hi;
        g_Al[idx] = __float2half_rn(v - __half2float(hi));
        return;
    }
    const int t = blockIdx.x - 2304;
    const int s0 = (t & 127) * 32;
    const int c0 = ((t >> 7) & 7) * 32;
    const int b = t >> 10;
    const int tx = tid & 31, ty = tid >> 5;         // 32 x 8
    const float* xb = x + ((size_t)b * CIN_ + c0) * HW_ + s0;
#pragma unroll
    for (int k = 0; k < 4; ++k)
        tile[ty + 8 * k][tx] = xb[(size_t)(ty + 8 * k) * HW_ + tx];
    __syncthreads();
#pragma unroll
    for (int k = 0; k < 4; ++k) {
        float v = tile[tx][ty + 8 * k];
        size_t o = ((size_t)b * HW_ + s0 + ty + 8 * k) * CIN_ + c0 + tx;
        g_X[o] = __float2half_rn(v);
    }
}

// ---------------------------------------------------------------------------
// Main fp16 implicit-GEMM. grid (2, 128), 512 threads (16 warps, 4/SMSP).
// Warp tile 32x64; 2 A-planes (hi/lo) share B fragments.
// ---------------------------------------------------------------------------
__global__ void __launch_bounds__(512, 1) conv_fp16_kernel(float* __restrict__ out) {
    extern __shared__ char smem[];
    const uint32_t sb = smem_u32(smem);
    const int tid = threadIdx.x;
    const int lane = tid & 31, warp = tid >> 5;
    const int m0 = blockIdx.x * BM;
    const int n0 = blockIdx.y * BN;
    const int b = n0 >> 10;
    const int pix0 = n0 & (NPIX_ - 1);

    if (tid < NSTAGE) mbar_init(sb + tid * 16, 1);
    asm volatile("fence.proxy.async.shared::cta;" ::: "memory");
    __syncthreads();

    const int pixL = pix0 + (tid & 255);
    const int ohL = pixL >> 5, owL = pixL & 31;
    const __half* gX0 = g_X + (size_t)b * HW_ * CIN_;

    auto load_stage = [&](int buf, int s) {
        const int p = s >> 2;
        const int cin0 = (s & 3) * KC;
        const int kh = p / 3, kw = p - kh * 3;
        const uint32_t st = sb + TILES_OFF + buf * STAGE_B;
        const uint32_t mb = sb + buf * 16;
        if (tid == 0) {
            int invalid = (kw == 0 ? 8 : 0)
                        + ((kh == 0 && pix0 == 0) ? 32 : 0)
                        - ((kw == 0 && kh == 0 && pix0 == 0) ? 1 : 0);
            uint32_t tx = 32768u + 128u * (uint32_t)(256 - invalid);
            mbar_expect_tx(mb, tx);
        }
        if (tid < 256) {
            // A rows: tid<128 -> hi plane row tid; tid in [128,256) -> lo plane
            const int ar = tid & 127;
            const __half* srcA = ((tid < 128) ? g_Ah : g_Al)
                               + (size_t)p * (COUT_ * CIN_) + (size_t)(m0 + ar) * CIN_ + cin0;
            bulk_g2s(st + ((tid < 128) ? AH_OFF : AL_OFF) + ar * ROW_B, srcA, 128, mb);
            // B row
            const int ih = ohL * 2 - 1 + kh;
            const int iw = owL * 2 - 1 + kw;
            const uint32_t dst = st + B_OFF2 + tid * ROW_B;
            if (((unsigned)ih < (unsigned)H_) && ((unsigned)iw < (unsigned)W_)) {
                bulk_g2s(dst, gX0 + (size_t)(ih * W_ + iw) * CIN_ + cin0, 128, mb);
            } else {
#pragma unroll
                for (int j = 0; j < 8; ++j)
                    asm volatile("st.shared.v4.b32 [%0], {%1, %1, %1, %1};"
                                 :: "r"(dst + j * 16), "r"(0u) : "memory");
            }
        }
    };

    float acc[2][8][4];
#pragma unroll
    for (int mi = 0; mi < 2; ++mi)
#pragma unroll
        for (int ni = 0; ni < 8; ++ni)
#pragma unroll
            for (int j = 0; j < 4; ++j) acc[mi][ni][j] = 0.0f;

    load_stage(0, 0);
    load_stage(1, 1);
    load_stage(2, 2);
    __syncthreads();   // zero-STS of initial stages visible

    const int mw = (warp >> 2) * 32;      // 0,32,64,96
    const int nw = (warp & 3) * 64;       // 0,64,128,192
    const int lg = lane >> 2;             // 0..7
    const int lc = lane & 3;              // 0..3

    int ib = 0;
    int ph[NSTAGE] = {0, 0, 0};

#pragma unroll 1
    for (int it = 0; it < NIT; ++it) {
        mbar_wait(sb + ib * 16, ph[ib]);
        ph[ib] ^= 1;
        const uint32_t st = sb + TILES_OFF + ib * STAGE_B;
#pragma unroll
        for (int ks = 0; ks < 4; ++ks) {
            const uint32_t kb = (uint32_t)(ks * 32 + lc * 4);
            uint32_t ah[2][4], al[2][4];
#pragma unroll
            for (int mi = 0; mi < 2; ++mi) {
                const uint32_t r0 = st + (mw + mi * 16 + lg) * ROW_B + kb;
                ah[mi][0] = lds32(r0);
                ah[mi][1] = lds32(r0 + 8 * ROW_B);
                ah[mi][2] = lds32(r0 + 16);
                ah[mi][3] = lds32(r0 + 8 * ROW_B + 16);
                const uint32_t r1 = r0 + AL_OFF;
                al[mi][0] = lds32(r1);
                al[mi][1] = lds32(r1 + 8 * ROW_B);
                al[mi][2] = lds32(r1 + 16);
                al[mi][3] = lds32(r1 + 8 * ROW_B + 16);
            }
#pragma unroll
            for (int ni = 0; ni < 8; ++ni) {
                const uint32_t rb = st + B_OFF2 + (nw + ni * 8 + lg) * ROW_B + kb;
                uint32_t b0 = lds32(rb);
                uint32_t b1 = lds32(rb + 16);
#pragma unroll
                for (int mi = 0; mi < 2; ++mi) {
                    mma_fp16(acc[mi][ni], ah[mi], b0, b1);
                    mma_fp16(acc[mi][ni], al[mi], b0, b1);
                }
            }
        }
        __syncthreads();                       // all warps done with buffer ib
        if (it + NSTAGE < NIT) load_stage(ib, it + NSTAGE);
        if (++ib == NSTAGE) ib = 0;
    }

    // ---- epilogue ----
    float* ob = out + (size_t)b * COUT_ * NPIX_;
#pragma unroll
    for (int mi = 0; mi < 2; ++mi) {
        const int cout0 = m0 + mw + mi * 16 + lg;
#pragma unroll
        for (int ni = 0; ni < 8; ++ni) {
            const int nc = pix0 + nw + ni * 8 + lc * 2;
            float2* p0 = (float2*)(ob + (size_t)cout0 * NPIX_ + nc);
            float2* p1 = (float2*)(ob + (size_t)(cout0 + 8) * NPIX_ + nc);
            *p0 = make_float2(acc[mi][ni][0], acc[mi][ni][1]);
            *p1 = make_float2(acc[mi][ni][2], acc[mi][ni][3]);
        }
    }
}

// ---------------------------------------------------------------------------
extern "C" void kernel_launch(void* const* d_in, const int* in_sizes, int n_in,
                              void* d_out, int out_size) {
    const float* x = (const float*)d_in[0];   // [32,256,64,64]
    const float* w = (const float*)d_in[1];   // [256,256,3,3]
    float* out = (float*)d_out;               // [32,256,32,32]

    cudaFuncSetAttribute(conv_fp16_kernel,
                         cudaFuncAttributeMaxDynamicSharedMemorySize, SMEM_TOTAL);

    transform_kernel<<<2304 + 32768, 256>>>(x, w);
    {
        dim3 grid(COUT_ / BM, (B_ * NPIX_) / BN);   // (2, 128)
        conv_fp16_kernel<<<grid, 512, SMEM_TOTAL>>>(out);
    }
}

// round 8
// speedup vs baseline: 1.0152x; 1.0152x over previous
#include <cuda_runtime.h>
#include <cuda_fp16.h>
#include <cstdint>

// ---------------------------------------------------------------------------
// B=32, CIN=256, COUT=256, 64x64 -> 32x32, 3x3 stride2 pad1 conv. Crop mask
// all-True => plain conv. fp16 m16n8k16 two-term split GEMM:
//   C = Ahi*Bhi + Alo*Bhi   (weights split hi/lo fp16, x single fp16)
// Round 8: ldmatrix.x4 fragment loads (4x fewer shared-load instrs, far less
// address ALU), half2-vectorized x-convert prologue.
// ---------------------------------------------------------------------------

#define B_    32
#define CIN_  256
#define COUT_ 256
#define H_    64
#define W_    64
#define HW_   4096
#define NPIX_ 1024

#define BM 128
#define BN 256
#define KC 64
#define NIT 36                 // 9 taps * 4 cin-chunks

// fp16 rows: 64 fp16 = 128B payload, 144B stride (16B-aligned, conflict-free)
#define ROW_B    144
#define AH_OFF   0
#define AL_OFF   (128 * ROW_B)             // 18432
#define B_OFF2   (2 * 128 * ROW_B)         // 36864
#define STAGE_B  (B_OFF2 + 256 * ROW_B)    // 73728
#define TILES_OFF 1024
#define NSTAGE   3
#define SMEM_TOTAL (TILES_OFF + NSTAGE * STAGE_B)   // 222208

__device__ __align__(128) __half g_Ah[9 * COUT_ * CIN_];        // [p][cout][cin]
__device__ __align__(128) __half g_Al[9 * COUT_ * CIN_];
__device__ __align__(128) __half g_X[(size_t)B_ * HW_ * CIN_];  // [b][s][cin]

// ---------------------------------------------------------------------------
__device__ __forceinline__ uint32_t smem_u32(const void* p) {
    uint32_t a;
    asm("{ .reg .u64 t; cvta.to.shared.u64 t, %1; cvt.u32.u64 %0, t; }" : "=r"(a) : "l"(p));
    return a;
}
__device__ __forceinline__ void bulk_g2s(uint32_t dst, const void* src, uint32_t bytes,
                                         uint32_t mbar) {
    asm volatile(
        "cp.async.bulk.shared::cluster.global.mbarrier::complete_tx::bytes "
        "[%0], [%1], %2, [%3];"
        :: "r"(dst), "l"(src), "r"(bytes), "r"(mbar) : "memory");
}
__device__ __forceinline__ void mbar_init(uint32_t a, uint32_t cnt) {
    asm volatile("mbarrier.init.shared.b64 [%0], %1;" :: "r"(a), "r"(cnt) : "memory");
}
__device__ __forceinline__ void mbar_expect_tx(uint32_t a, uint32_t tx) {
    asm volatile("mbarrier.arrive.expect_tx.shared.b64 _, [%0], %1;"
                 :: "r"(a), "r"(tx) : "memory");
}
__device__ __forceinline__ void mbar_wait(uint32_t a, uint32_t parity) {
    asm volatile(
        "{\n\t.reg .pred P1;\n\t"
        "W_%=:\n\t"
        "mbarrier.try_wait.parity.acquire.cta.shared::cta.b64 P1, [%0], %1, 0x989680;\n\t"
        "@!P1 bra W_%=;\n\t}"
        :: "r"(a), "r"(parity) : "memory");
}
__device__ __forceinline__ void mma_fp16(float* d, const uint32_t* a, uint32_t b0, uint32_t b1) {
    asm volatile(
        "mma.sync.aligned.m16n8k16.row.col.f32.f16.f16.f32 "
        "{%0,%1,%2,%3}, {%4,%5,%6,%7}, {%8,%9}, {%0,%1,%2,%3};"
        : "+f"(d[0]), "+f"(d[1]), "+f"(d[2]), "+f"(d[3])
        : "r"(a[0]), "r"(a[1]), "r"(a[2]), "r"(a[3]), "r"(b0), "r"(b1));
}
__device__ __forceinline__ void ldm4(uint32_t* r, uint32_t addr) {
    asm volatile("ldmatrix.sync.aligned.m8n8.x4.shared.b16 {%0,%1,%2,%3}, [%4];"
                 : "=r"(r[0]), "=r"(r[1]), "=r"(r[2]), "=r"(r[3]) : "r"(addr));
}

// ---------------------------------------------------------------------------
// Fused prologue: blocks [0, 2304) -> weight split; [2304, 35072) -> x convert
// ---------------------------------------------------------------------------
__global__ void transform_kernel(const float* __restrict__ x, const float* __restrict__ w) {
    __shared__ float tile[32][33];   // tile[c_local][s_local]
    const int tid = threadIdx.x;
    if (blockIdx.x < 2304) {
        int idx = blockIdx.x * 256 + tid;           // over [p][cout][cin]
        int cin = idx & 255;
        int cout = (idx >> 8) & 255;
        int p = idx >> 16;
        float v = w[cout * (CIN_ * 9) + cin * 9 + p];
        __half hi = __float2half_rn(v);
        g_Ah[idx] = hi;
        g_Al[idx] = __float2half_rn(v - __half2float(hi));
        return;
    }
    const int t = blockIdx.x - 2304;
    const int s0 = (t & 127) * 32;
    const int c0 = ((t >> 7) & 7) * 32;
    const int b = t >> 10;
    const int tx = tid & 31, ty = tid >> 5;         // 32 x 8
    const float* xb = x + ((size_t)b * CIN_ + c0) * HW_ + s0;
#pragma unroll
    for (int k = 0; k < 4; ++k)
        tile[ty + 8 * k][tx] = xb[(size_t)(ty + 8 * k) * HW_ + tx];   // tile[c][s]
    __syncthreads();
    // write half2: thread -> c pair (2*(tid&15)), s = (tid>>4) + 16*k
    const int c2 = (tid & 15) * 2;
#pragma unroll
    for (int k = 0; k < 2; ++k) {
        const int s = (tid >> 4) + 16 * k;
        __half2 v = __floats2half2_rn(tile[c2][s], tile[c2 + 1][s]);
        size_t o = ((size_t)b * HW_ + s0 + s) * CIN_ + c0 + c2;
        *(__half2*)(g_X + o) = v;
    }
}

// ---------------------------------------------------------------------------
// Main fp16 implicit-GEMM. grid (2, 128), 512 threads (16 warps, 4/SMSP).
// Warp tile 32x64; fragments via ldmatrix.x4.
// ---------------------------------------------------------------------------
__global__ void __launch_bounds__(512, 1) conv_fp16_kernel(float* __restrict__ out) {
    extern __shared__ char smem[];
    const uint32_t sb = smem_u32(smem);
    const int tid = threadIdx.x;
    const int lane = tid & 31, warp = tid >> 5;
    const int m0 = blockIdx.x * BM;
    const int n0 = blockIdx.y * BN;
    const int b = n0 >> 10;
    const int pix0 = n0 & (NPIX_ - 1);

    if (tid < NSTAGE) mbar_init(sb + tid * 16, 1);
    asm volatile("fence.proxy.async.shared::cta;" ::: "memory");
    __syncthreads();

    const int pixL = pix0 + (tid & 255);
    const int ohL = pixL >> 5, owL = pixL & 31;
    const __half* gX0 = g_X + (size_t)b * HW_ * CIN_;

    auto load_stage = [&](int buf, int s) {
        const int p = s >> 2;
        const int cin0 = (s & 3) * KC;
        const int kh = p / 3, kw = p - kh * 3;
        const uint32_t st = sb + TILES_OFF + buf * STAGE_B;
        const uint32_t mb = sb + buf * 16;
        if (tid == 0) {
            int invalid = (kw == 0 ? 8 : 0)
                        + ((kh == 0 && pix0 == 0) ? 32 : 0)
                        - ((kw == 0 && kh == 0 && pix0 == 0) ? 1 : 0);
            uint32_t tx = 32768u + 128u * (uint32_t)(256 - invalid);
            mbar_expect_tx(mb, tx);
        }
        if (tid < 256) {
            const int ar = tid & 127;
            const __half* srcA = ((tid < 128) ? g_Ah : g_Al)
                               + (size_t)p * (COUT_ * CIN_) + (size_t)(m0 + ar) * CIN_ + cin0;
            bulk_g2s(st + ((tid < 128) ? AH_OFF : AL_OFF) + ar * ROW_B, srcA, 128, mb);
            const int ih = ohL * 2 - 1 + kh;
            const int iw = owL * 2 - 1 + kw;
            const uint32_t dst = st + B_OFF2 + tid * ROW_B;
            if (((unsigned)ih < (unsigned)H_) && ((unsigned)iw < (unsigned)W_)) {
                bulk_g2s(dst, gX0 + (size_t)(ih * W_ + iw) * CIN_ + cin0, 128, mb);
            } else {
#pragma unroll
                for (int j = 0; j < 8; ++j)
                    asm volatile("st.shared.v4.b32 [%0], {%1, %1, %1, %1};"
                                 :: "r"(dst + j * 16), "r"(0u) : "memory");
            }
        }
    };

    float acc[2][8][4];
#pragma unroll
    for (int mi = 0; mi < 2; ++mi)
#pragma unroll
        for (int ni = 0; ni < 8; ++ni)
#pragma unroll
            for (int j = 0; j < 4; ++j) acc[mi][ni][j] = 0.0f;

    load_stage(0, 0);
    load_stage(1, 1);
    load_stage(2, 2);
    __syncthreads();

    const int mw = (warp >> 2) * 32;      // 0,32,64,96
    const int nw = (warp & 3) * 64;       // 0,64,128,192
    // lane-invariant ldmatrix offsets within a stage
    uint32_t aOff[2], bOff[4];
#pragma unroll
    for (int mi = 0; mi < 2; ++mi)
        aOff[mi] = (uint32_t)((mw + mi * 16 + (lane & 15)) * ROW_B + (lane >> 4) * 16);
#pragma unroll
    for (int nj = 0; nj < 4; ++nj)
        bOff[nj] = (uint32_t)(B_OFF2
                 + (nw + nj * 16 + (lane & 7) + (lane >> 4) * 8) * ROW_B
                 + ((lane >> 3) & 1) * 16);

    int ib = 0;
    int ph[NSTAGE] = {0, 0, 0};

#pragma unroll 1
    for (int it = 0; it < NIT; ++it) {
        mbar_wait(sb + ib * 16, ph[ib]);
        ph[ib] ^= 1;
        const uint32_t st = sb + TILES_OFF + ib * STAGE_B;
#pragma unroll
        for (int ks = 0; ks < 4; ++ks) {
            const uint32_t kb = (uint32_t)(ks * 32);
            uint32_t ah[2][4], al[2][4], bf[4][4];
#pragma unroll
            for (int mi = 0; mi < 2; ++mi) {
                ldm4(ah[mi], st + aOff[mi] + kb);
                ldm4(al[mi], st + AL_OFF + aOff[mi] + kb);
            }
#pragma unroll
            for (int nj = 0; nj < 4; ++nj)
                ldm4(bf[nj], st + bOff[nj] + kb);
#pragma unroll
            for (int nj = 0; nj < 4; ++nj)
#pragma unroll
                for (int s2 = 0; s2 < 2; ++s2) {
                    const int ni = nj * 2 + s2;
                    const uint32_t b0 = bf[nj][s2 * 2];
                    const uint32_t b1 = bf[nj][s2 * 2 + 1];
#pragma unroll
                    for (int mi = 0; mi < 2; ++mi) {
                        mma_fp16(acc[mi][ni], ah[mi], b0, b1);
                        mma_fp16(acc[mi][ni], al[mi], b0, b1);
                    }
                }
        }
        __syncthreads();
        if (it + NSTAGE < NIT) load_stage(ib, it + NSTAGE);
        if (++ib == NSTAGE) ib = 0;
    }

    // ---- epilogue ----
    const int lg = lane >> 2;
    const int lc = lane & 3;
    float* ob = out + (size_t)b * COUT_ * NPIX_;
#pragma unroll
    for (int mi = 0; mi < 2; ++mi) {
        const int cout0 = m0 + mw + mi * 16 + lg;
#pragma unroll
        for (int ni = 0; ni < 8; ++ni) {
            const int nc = pix0 + nw + ni * 8 + lc * 2;
            float2* p0 = (float2*)(ob + (size_t)cout0 * NPIX_ + nc);
            float2* p1 = (float2*)(ob + (size_t)(cout0 + 8) * NPIX_ + nc);
            *p0 = make_float2(acc[mi][ni][0], acc[mi][ni][1]);
            *p1 = make_float2(acc[mi][ni][2], acc[mi][ni][3]);
        }
    }
}

// ---------------------------------------------------------------------------
extern "C" void kernel_launch(void* const* d_in, const int* in_sizes, int n_in,
                              void* d_out, int out_size) {
    const float* x = (const float*)d_in[0];   // [32,256,64,64]
    const float* w = (const float*)d_in[1];   // [256,256,3,3]
    float* out = (float*)d_out;               // [32,256,32,32]

    cudaFuncSetAttribute(conv_fp16_kernel,
                         cudaFuncAttributeMaxDynamicSharedMemorySize, SMEM_TOTAL);

    transform_kernel<<<2304 + 32768, 256>>>(x, w);
    {
        dim3 grid(COUT_ / BM, (B_ * NPIX_) / BN);   // (2, 128)
        conv_fp16_kernel<<<grid, 512, SMEM_TOTAL>>>(out);
    }
}